// round 14
// baseline (speedup 1.0000x reference)
#include <cuda_runtime.h>
#include <cuda_bf16.h>
#include <math.h>
#include <stdint.h>

// ---------------- problem constants ----------------
// B=16, Cmel=80, Ctxt=256, Catt=80, T1=800, T2=200
#define NB   16
#define T1D  800
#define T2D  200

// t-major image strides (bf16 elems). Rule: (stride*2 bytes /4) mod 32 in {4,12,20,28}
#define XK_P 264   // keys    256+8
#define XQ_P 88    // queries  80+8
#define K1_P 536   // k1      512+24
#define Q1_P 168   // q1      160+8
#define AT_P 88    // q/k attention images 80+8

// ---------------- scratch (no allocation allowed) ----------------
__device__ __nv_bfloat16 g_wimg[522752];           // repacked weights
__device__ __nv_bfloat16 g_xk [NB * T2D * XK_P];   // keys bf16 t-major
__device__ __nv_bfloat16 g_xq [NB * T1D * XQ_P];   // queries bf16 t-major
__device__ __nv_bfloat16 g_k1i[NB * T2D * K1_P];   // key conv1 out, t-major
__device__ __nv_bfloat16 g_q1i[NB * T1D * Q1_P];   // query conv1 out, t-major
__device__ __nv_bfloat16 g_kki[NB * T2D * AT_P];   // k, t-major
__device__ __nv_bfloat16 g_qqi[NB * T1D * AT_P];   // q, t-major
__device__ float         g_k2 [NB * T2D];          // ||k||^2

// weight image section offsets (elems)
#define OFF_KC1 0
#define OFF_K11 417792
#define OFF_QC3 460032
#define OFF_Q12 502272
#define OFF_Q13 515712
#define W_TOTAL 522752

// ---------------- helpers ----------------
__device__ __forceinline__ uint32_t smem_u32(const void* p) {
    uint32_t a;
    asm("{ .reg .u64 t; cvta.to.shared.u64 t, %1; cvt.u32.u64 %0, t; }" : "=r"(a) : "l"(p));
    return a;
}
__device__ __forceinline__ void ldsm_x4(uint32_t& r0, uint32_t& r1, uint32_t& r2, uint32_t& r3,
                                        uint32_t addr) {
    asm volatile("ldmatrix.sync.aligned.m8n8.x4.shared.b16 {%0,%1,%2,%3}, [%4];"
                 : "=r"(r0), "=r"(r1), "=r"(r2), "=r"(r3) : "r"(addr));
}
__device__ __forceinline__ void ldsm_x2(uint32_t& r0, uint32_t& r1, uint32_t addr) {
    asm volatile("ldmatrix.sync.aligned.m8n8.x2.shared.b16 {%0,%1}, [%2];"
                 : "=r"(r0), "=r"(r1) : "r"(addr));
}
__device__ __forceinline__ void mma16816(float* c, uint32_t a0, uint32_t a1, uint32_t a2,
                                         uint32_t a3, uint32_t b0, uint32_t b1) {
    asm volatile("mma.sync.aligned.m16n8k16.row.col.f32.bf16.bf16.f32 "
                 "{%0,%1,%2,%3}, {%4,%5,%6,%7}, {%8,%9}, {%0,%1,%2,%3};"
                 : "+f"(c[0]), "+f"(c[1]), "+f"(c[2]), "+f"(c[3])
                 : "r"(a0), "r"(a1), "r"(a2), "r"(a3), "r"(b0), "r"(b1));
}

// ---- register fragment batch: A(16x16) + 13 B tiles (104 n-cols) ----
__device__ __forceinline__ void ldA(uint32_t (&av)[4], uint32_t addr) {
    ldsm_x4(av[0], av[1], av[2], av[3], addr);
}
template<int STR>
__device__ __forceinline__ void ldB(uint32_t (&bv)[26], uint32_t xs_u, int row0, int colbase,
                                    int b_row, int b_kh, int b_row2) {
    #pragma unroll
    for (int p = 0; p < 6; ++p)
        ldsm_x4(bv[4 * p], bv[4 * p + 1], bv[4 * p + 2], bv[4 * p + 3],
                xs_u + (uint32_t)(((row0 + p * 16 + b_row) * STR + colbase + b_kh) * 2));
    ldsm_x2(bv[24], bv[25],
            xs_u + (uint32_t)(((row0 + 96 + b_row2) * STR + colbase + b_kh) * 2));
}
__device__ __forceinline__ void applyAB(float (&acc)[13][4], const uint32_t (&av)[4],
                                        const uint32_t (&bv)[26]) {
    #pragma unroll
    for (int p = 0; p < 6; ++p) {
        mma16816(acc[2 * p],     av[0], av[1], av[2], av[3], bv[4 * p],     bv[4 * p + 1]);
        mma16816(acc[2 * p + 1], av[0], av[1], av[2], av[3], bv[4 * p + 2], bv[4 * p + 3]);
    }
    mma16816(acc[12], av[0], av[1], av[2], av[3], bv[24], bv[25]);
}

// ---------------- weight repack: fp32 -> bf16 smem-image layout ----------------
__global__ void prep_w_kernel(const float* __restrict__ kw1, const float* __restrict__ kw2,
                              const float* __restrict__ qw1, const float* __restrict__ qw2,
                              const float* __restrict__ qw3)
{
    int idx = blockIdx.x * blockDim.x + threadIdx.x;
    if (idx >= W_TOTAL) return;
    float v = 0.f;
    if (idx < OFF_K11) {                       // key conv1: [y4][cc2][s3][co128][k136]
        int l = idx;
        int k = l % 136; l /= 136;
        int co = l % 128; l /= 128;
        int s = l % 3; l /= 3;
        int cc = l % 2; int y = l / 2;
        if (k < 128) v = kw1[(size_t)(y * 128 + co) * 768 + (cc * 128 + k) * 3 + s];
    } else if (idx < OFF_QC3) {                // key 1x1: [cc2][co80][k264]
        int l = idx - OFF_K11;
        int k = l % 264; l /= 264;
        int co = l % 80; int cc = l / 80;
        if (k < 256) v = kw2[(size_t)co * 512 + cc * 256 + k];
    } else if (idx < OFF_Q12) {                // q conv3: [y2][s3][co80][k88]
        int l = idx - OFF_QC3;
        int k = l % 88; l /= 88;
        int co = l % 80; l /= 80;
        int s = l % 3; int y = l / 3;
        if (k < 80) v = qw1[(size_t)(y * 80 + co) * 240 + k * 3 + s];
    } else if (idx < OFF_Q13) {                // q 1x1 a: [co80][k168]
        int l = idx - OFF_Q12;
        int k = l % 168; int co = l / 168;
        if (k < 160) v = qw2[(size_t)co * 160 + k];
    } else {                                   // q 1x1 b: [co80][k88]
        int l = idx - OFF_Q13;
        int k = l % 88; int co = l / 88;
        if (k < 80) v = qw3[(size_t)co * 80 + k];
    }
    g_wimg[idx] = __float2bfloat16(v);
}

// ---------------- input transpose: fp32 [C][T] -> bf16 [T][CP] ----------------
__global__ void transpose_bf_kernel(const float* __restrict__ x, __nv_bfloat16* __restrict__ out,
                                    int C, int T, int CP)
{
    __shared__ float tile[32][33];
    int b = blockIdx.z;
    int t0 = blockIdx.x * 32, c0 = blockIdx.y * 32;
    int tx = threadIdx.x, ty = threadIdx.y;
    #pragma unroll
    for (int j = 0; j < 4; ++j) {
        int c = c0 + ty + j * 8, t = t0 + tx;
        tile[ty + j * 8][tx] = (c < C && t < T) ? x[((size_t)b * C + c) * T + t] : 0.f;
    }
    __syncthreads();
    #pragma unroll
    for (int j = 0; j < 4; ++j) {
        int t = t0 + ty + j * 8, c = c0 + tx;
        if (t < T && c < C)
            out[((size_t)b * T + t) * CP + c] = __float2bfloat16(tile[tx][ty + j * 8]);
    }
}

// ---------------- k=3 conv + ReLU, image in -> image out (t-major) ----------------
// Pipelined per tap-section: 3 sections of KC/16 steps; double-buffered frags.
template<int CIN, int CINP, int KC, int WM, int OUTP>
__global__ __launch_bounds__(32 * WM)
void conv3_img_kernel(const __nv_bfloat16* __restrict__ xin, int wimg_off,
                      const float* __restrict__ bias, __nv_bfloat16* __restrict__ yimg, int T)
{
    constexpr int THREADS = 32 * WM;
    constexpr int BM = 16 * WM, BN = 104, ROWS = BN + 2;
    constexpr int KCP = KC + 8, NCH = CIN / KC;
    constexpr int XV = CINP / 8;
    constexpr int WCH = 3 * BM * KCP;
    constexpr int BMP = BM + 8;
    constexpr int KC16 = KC / 16;

    extern __shared__ __align__(16) char sm[];
    __nv_bfloat16* xs = (__nv_bfloat16*)sm;
    __nv_bfloat16* ws = xs + ROWS * CINP;
    __nv_bfloat16* os = xs;

    const int b = blockIdx.z, yb = blockIdx.y, t0 = blockIdx.x * BN;
    const int co0 = yb * BM;
    const int tid = threadIdx.x, lane = tid & 31, wm = tid >> 5;

    float acc[13][4];
    #pragma unroll
    for (int nt = 0; nt < 13; ++nt)
        #pragma unroll
        for (int i = 0; i < 4; ++i) acc[nt][i] = 0.f;

    const uint4 z4 = make_uint4(0, 0, 0, 0);
    for (int idx = tid; idx < ROWS * XV; idx += THREADS) {
        int r = idx / XV, c = idx - r * XV;
        int t = t0 + r - 1;
        uint4 v = z4;
        if (t >= 0 && t < T) v = ((const uint4*)(xin + ((size_t)b * T + t) * CINP))[c];
        ((uint4*)xs)[idx] = v;
    }

    const uint32_t xs_u = smem_u32(xs), ws_u = smem_u32(ws);
    const int a_row = lane & 15, a_kh = (lane >> 4) * 8;
    const int b_row = (lane & 7) + ((lane >> 4) & 1) * 8;
    const int b_kh = ((lane >> 3) & 1) * 8;
    const int b_row2 = lane & 7;

    for (int cc = 0; cc < NCH; ++cc) {
        if (cc) __syncthreads();
        const uint4* wsrc = (const uint4*)(g_wimg + wimg_off + (size_t)(yb * NCH + cc) * WCH);
        for (int i = tid; i < WCH / 8; i += THREADS) ((uint4*)ws)[i] = wsrc[i];
        __syncthreads();

        // per-tap pipelined sections (bounded unroll scope)
        #pragma unroll
        for (int s = 0; s < 3; ++s) {
            uint32_t av[2][4], bv[2][26];
            ldA(av[0], ws_u + (uint32_t)(((s * BM + wm * 16 + a_row) * KCP + a_kh) * 2));
            ldB<CINP>(bv[0], xs_u, s, cc * KC, b_row, b_kh, b_row2);
            #pragma unroll
            for (int st = 0; st < KC16; ++st) {
                const int cur = st & 1, nxt = cur ^ 1;
                if (st + 1 < KC16) {
                    ldA(av[nxt],
                        ws_u + (uint32_t)(((s * BM + wm * 16 + a_row) * KCP
                                           + (st + 1) * 16 + a_kh) * 2));
                    ldB<CINP>(bv[nxt], xs_u, s, cc * KC + (st + 1) * 16,
                              b_row, b_kh, b_row2);
                }
                applyAB(acc, av[cur], bv[cur]);
            }
        }
    }

    __syncthreads();
    const int g = lane >> 2, tg = lane & 3;
    const int coA = wm * 16 + g, coB = coA + 8;
    const float bA = bias[co0 + coA], bB = bias[co0 + coB];
    #pragma unroll
    for (int nt = 0; nt < 13; ++nt) {
        int tl = nt * 8 + tg * 2;
        os[tl * BMP + coA]       = __float2bfloat16(fmaxf(acc[nt][0] + bA, 0.f));
        os[(tl + 1) * BMP + coA] = __float2bfloat16(fmaxf(acc[nt][1] + bA, 0.f));
        os[tl * BMP + coB]       = __float2bfloat16(fmaxf(acc[nt][2] + bB, 0.f));
        os[(tl + 1) * BMP + coB] = __float2bfloat16(fmaxf(acc[nt][3] + bB, 0.f));
    }
    __syncthreads();
    constexpr int OV = BM / 8;
    for (int idx = tid; idx < BN * OV; idx += THREADS) {
        int r = idx / OV, c = idx - r * OV;
        int t = t0 + r;
        if (t < T)
            ((uint4*)(yimg + ((size_t)b * T + t) * OUTP + co0))[c] =
                ((const uint4*)(os + r * BMP))[c];
    }
}

// ---------------- key 1x1 (512->80) + fused ||k||^2, t-major image out ----------------
__global__ __launch_bounds__(160)
void k11_kernel(const __nv_bfloat16* __restrict__ xin,
                const float* __restrict__ bias, __nv_bfloat16* __restrict__ yimg,
                float* __restrict__ k2, int T)
{
    constexpr int THREADS = 160, BN = 104;
    constexpr int CINP = K1_P, KC = 256, KCP = KC + 8, NCH = 2;
    constexpr int XV = CINP / 8;
    constexpr int WCH = 80 * KCP;
    constexpr int NST = KC / 16;   // 16 per chunk

    extern __shared__ __align__(16) char sm[];
    __nv_bfloat16* xs = (__nv_bfloat16*)sm;
    __nv_bfloat16* ws = xs + BN * CINP;
    float* ss = (float*)(ws + WCH);
    __nv_bfloat16* os = xs;

    const int b = blockIdx.z, t0 = blockIdx.x * BN;
    const int tid = threadIdx.x, lane = tid & 31, wm = tid >> 5;

    float acc[13][4];
    #pragma unroll
    for (int nt = 0; nt < 13; ++nt)
        #pragma unroll
        for (int i = 0; i < 4; ++i) acc[nt][i] = 0.f;

    for (int i = tid; i < BN; i += THREADS) ss[i] = 0.f;

    const uint4 z4 = make_uint4(0, 0, 0, 0);
    for (int idx = tid; idx < BN * XV; idx += THREADS) {
        int r = idx / XV, c = idx - r * XV;
        int t = t0 + r;
        uint4 v = z4;
        if (t < T) v = ((const uint4*)(xin + ((size_t)b * T + t) * CINP))[c];
        ((uint4*)xs)[idx] = v;
    }

    const uint32_t xs_u = smem_u32(xs), ws_u = smem_u32(ws);
    const int a_row = lane & 15, a_kh = (lane >> 4) * 8;
    const int b_row = (lane & 7) + ((lane >> 4) & 1) * 8;
    const int b_kh = ((lane >> 3) & 1) * 8;
    const int b_row2 = lane & 7;

    for (int cc = 0; cc < NCH; ++cc) {
        if (cc) __syncthreads();
        const uint4* wsrc = (const uint4*)(g_wimg + OFF_K11 + (size_t)cc * WCH);
        for (int i = tid; i < WCH / 8; i += THREADS) ((uint4*)ws)[i] = wsrc[i];
        __syncthreads();

        uint32_t av[2][4], bv[2][26];
        ldA(av[0], ws_u + (uint32_t)(((wm * 16 + a_row) * KCP + a_kh) * 2));
        ldB<CINP>(bv[0], xs_u, 0, cc * KC, b_row, b_kh, b_row2);
        #pragma unroll
        for (int st = 0; st < NST; ++st) {
            const int cur = st & 1, nxt = cur ^ 1;
            if (st + 1 < NST) {
                ldA(av[nxt],
                    ws_u + (uint32_t)(((wm * 16 + a_row) * KCP + (st + 1) * 16 + a_kh) * 2));
                ldB<CINP>(bv[nxt], xs_u, 0, cc * KC + (st + 1) * 16, b_row, b_kh, b_row2);
            }
            applyAB(acc, av[cur], bv[cur]);
        }
    }

    __syncthreads();
    const int g = lane >> 2, tg = lane & 3;
    const int coA = wm * 16 + g, coB = coA + 8;
    const float bA = bias[coA], bB = bias[coB];
    #pragma unroll
    for (int nt = 0; nt < 13; ++nt) {
        int tl = nt * 8 + tg * 2;
        float v0 = acc[nt][0] + bA, v1 = acc[nt][1] + bA;
        float v2 = acc[nt][2] + bB, v3 = acc[nt][3] + bB;
        os[tl * AT_P + coA]       = __float2bfloat16(v0);
        os[(tl + 1) * AT_P + coA] = __float2bfloat16(v1);
        os[tl * AT_P + coB]       = __float2bfloat16(v2);
        os[(tl + 1) * AT_P + coB] = __float2bfloat16(v3);
        float s0 = v0 * v0 + v2 * v2;
        float s1 = v1 * v1 + v3 * v3;
        #pragma unroll
        for (int off = 4; off < 32; off <<= 1) {
            s0 += __shfl_xor_sync(0xffffffff, s0, off);
            s1 += __shfl_xor_sync(0xffffffff, s1, off);
        }
        if (g == 0) {
            atomicAdd(&ss[tl], s0);
            atomicAdd(&ss[tl + 1], s1);
        }
    }
    __syncthreads();
    constexpr int OV = AT_P / 8;
    for (int idx = tid; idx < BN * OV; idx += THREADS) {
        int r = idx / OV, c = idx - r * OV;
        int t = t0 + r;
        if (t < T)
            ((uint4*)(yimg + ((size_t)b * T + t) * AT_P))[c] =
                ((const uint4*)(os + r * AT_P))[c];
    }
    for (int i = tid; i < BN; i += THREADS) {
        int t = t0 + i;
        if (t < T) k2[b * T2D + t] = ss[i];
    }
}

// ---------------- fused query 1x1 (160->80 relu) -> 1x1 (80->80), t-major out ----------------
__global__ __launch_bounds__(160)
void qfused_kernel(const __nv_bfloat16* __restrict__ xin, const float* __restrict__ b2,
                   const float* __restrict__ b3, __nv_bfloat16* __restrict__ yimg, int T)
{
    constexpr int THREADS = 160, BN = 104;
    constexpr int CINP1 = Q1_P;   // 168
    constexpr int KCP2 = 168, KCP3 = 88, QMP = 88;

    extern __shared__ __align__(16) char sm[];
    __nv_bfloat16* xs  = (__nv_bfloat16*)sm;          // [104][168]
    __nv_bfloat16* w2s = xs + BN * CINP1;             // [80][168]
    __nv_bfloat16* qms = w2s + 80 * KCP2;             // [104][88]
    __nv_bfloat16* w3s = qms + BN * QMP;              // [80][88]
    __nv_bfloat16* os  = xs;

    const int b = blockIdx.z, t0 = blockIdx.x * BN;
    const int tid = threadIdx.x, lane = tid & 31, wm = tid >> 5;

    float acc[13][4];
    #pragma unroll
    for (int nt = 0; nt < 13; ++nt)
        #pragma unroll
        for (int i = 0; i < 4; ++i) acc[nt][i] = 0.f;

    const uint4 z4 = make_uint4(0, 0, 0, 0);
    constexpr int XV = CINP1 / 8;
    for (int idx = tid; idx < BN * XV; idx += THREADS) {
        int r = idx / XV, c = idx - r * XV;
        int t = t0 + r;
        uint4 v = z4;
        if (t < T) v = ((const uint4*)(xin + ((size_t)b * T + t) * CINP1))[c];
        ((uint4*)xs)[idx] = v;
    }
    {
        const uint4* s2 = (const uint4*)(g_wimg + OFF_Q12);
        for (int i = tid; i < 80 * KCP2 / 8; i += THREADS) ((uint4*)w2s)[i] = s2[i];
        const uint4* s3 = (const uint4*)(g_wimg + OFF_Q13);
        for (int i = tid; i < 80 * KCP3 / 8; i += THREADS) ((uint4*)w3s)[i] = s3[i];
    }
    __syncthreads();

    const uint32_t xs_u = smem_u32(xs), w2_u = smem_u32(w2s);
    const uint32_t qm_u = smem_u32(qms), w3_u = smem_u32(w3s);
    const int a_row = lane & 15, a_kh = (lane >> 4) * 8;
    const int b_row = (lane & 7) + ((lane >> 4) & 1) * 8;
    const int b_kh = ((lane >> 3) & 1) * 8;
    const int b_row2 = lane & 7;
    const int g = lane >> 2, tg = lane & 3;
    const int coA = wm * 16 + g, coB = coA + 8;

    // stage 1: q1 (160) -> qm (80), relu  (10 pipelined steps)
    {
        uint32_t av[2][4], bv[2][26];
        ldA(av[0], w2_u + (uint32_t)(((wm * 16 + a_row) * KCP2 + a_kh) * 2));
        ldB<CINP1>(bv[0], xs_u, 0, 0, b_row, b_kh, b_row2);
        #pragma unroll
        for (int st = 0; st < 10; ++st) {
            const int cur = st & 1, nxt = cur ^ 1;
            if (st + 1 < 10) {
                ldA(av[nxt],
                    w2_u + (uint32_t)(((wm * 16 + a_row) * KCP2 + (st + 1) * 16 + a_kh) * 2));
                ldB<CINP1>(bv[nxt], xs_u, 0, (st + 1) * 16, b_row, b_kh, b_row2);
            }
            applyAB(acc, av[cur], bv[cur]);
        }
    }
    {
        const float bA = b2[coA], bB = b2[coB];
        #pragma unroll
        for (int nt = 0; nt < 13; ++nt) {
            int tl = nt * 8 + tg * 2;
            qms[tl * QMP + coA]       = __float2bfloat16(fmaxf(acc[nt][0] + bA, 0.f));
            qms[(tl + 1) * QMP + coA] = __float2bfloat16(fmaxf(acc[nt][1] + bA, 0.f));
            qms[tl * QMP + coB]       = __float2bfloat16(fmaxf(acc[nt][2] + bB, 0.f));
            qms[(tl + 1) * QMP + coB] = __float2bfloat16(fmaxf(acc[nt][3] + bB, 0.f));
            #pragma unroll
            for (int i = 0; i < 4; ++i) acc[nt][i] = 0.f;
        }
    }
    __syncthreads();

    // stage 2: qm (80) -> q (80)  (5 pipelined steps)
    {
        uint32_t av[2][4], bv[2][26];
        ldA(av[0], w3_u + (uint32_t)(((wm * 16 + a_row) * KCP3 + a_kh) * 2));
        ldB<QMP>(bv[0], qm_u, 0, 0, b_row, b_kh, b_row2);
        #pragma unroll
        for (int st = 0; st < 5; ++st) {
            const int cur = st & 1, nxt = cur ^ 1;
            if (st + 1 < 5) {
                ldA(av[nxt],
                    w3_u + (uint32_t)(((wm * 16 + a_row) * KCP3 + (st + 1) * 16 + a_kh) * 2));
                ldB<QMP>(bv[nxt], qm_u, 0, (st + 1) * 16, b_row, b_kh, b_row2);
            }
            applyAB(acc, av[cur], bv[cur]);
        }
    }
    {
        const float bA = b3[coA], bB = b3[coB];
        #pragma unroll
        for (int nt = 0; nt < 13; ++nt) {
            int tl = nt * 8 + tg * 2;
            os[tl * AT_P + coA]       = __float2bfloat16(acc[nt][0] + bA);
            os[(tl + 1) * AT_P + coA] = __float2bfloat16(acc[nt][1] + bA);
            os[tl * AT_P + coB]       = __float2bfloat16(acc[nt][2] + bB);
            os[(tl + 1) * AT_P + coB] = __float2bfloat16(acc[nt][3] + bB);
        }
    }
    __syncthreads();
    constexpr int OV = AT_P / 8;
    for (int idx = tid; idx < BN * OV; idx += THREADS) {
        int r = idx / OV, c = idx - r * OV;
        int t = t0 + r;
        if (t < T)
            ((uint4*)(yimg + ((size_t)b * T + t) * AT_P))[c] =
                ((const uint4*)(os + r * AT_P))[c];
    }
}

// ---------------- attention: mma logits + fused log_softmax + log(prior) ----------------
__global__ __launch_bounds__(128)
void attn_mma_kernel(const __nv_bfloat16* __restrict__ qimg,
                     const __nv_bfloat16* __restrict__ kimg,
                     const float* __restrict__ k2, const float* __restrict__ prior,
                     float* __restrict__ out)
{
    constexpr int KROWS = 208;
    __shared__ __nv_bfloat16 ks[KROWS * AT_P];
    __shared__ __nv_bfloat16 qs[32 * AT_P];
    __shared__ float k2s[T2D];
    __shared__ float redm[2][32], reds[2][32];

    const int b = blockIdx.y, t1base = blockIdx.x * 32;
    const int tid = threadIdx.x, lane = tid & 31, warp = tid >> 5;
    const int wm = warp & 1, wn = warp >> 1;

    constexpr int KV = AT_P / 8;
    const uint4 z4 = make_uint4(0, 0, 0, 0);
    for (int idx = tid; idx < KROWS * KV; idx += 128) {
        int r = idx / KV, c = idx - r * KV;
        uint4 v = z4;
        if (r < T2D) v = ((const uint4*)(kimg + ((size_t)b * T2D + r) * AT_P))[c];
        ((uint4*)ks)[idx] = v;
    }
    for (int idx = tid; idx < 32 * KV; idx += 128) {
        int r = idx / KV, c = idx - r * KV;
        ((uint4*)qs)[idx] = ((const uint4*)(qimg + ((size_t)b * T1D + t1base + r) * AT_P))[c];
    }
    for (int i = tid; i < T2D; i += 128) k2s[i] = k2[b * T2D + i];
    __syncthreads();

    float acc[13][4];
    #pragma unroll
    for (int nt = 0; nt < 13; ++nt)
        #pragma unroll
        for (int i = 0; i < 4; ++i) acc[nt][i] = 0.f;

    const uint32_t qs_u = smem_u32(qs), ks_u = smem_u32(ks);
    const int a_row = lane & 15, a_kh = (lane >> 4) * 8;
    const int b_row = (lane & 7) + ((lane >> 4) & 1) * 8;
    const int b_kh = ((lane >> 3) & 1) * 8;
    const int b_row2 = lane & 7;

    {
        uint32_t av[2][4], bv[2][26];
        ldA(av[0], qs_u + (uint32_t)(((wm * 16 + a_row) * AT_P + a_kh) * 2));
        ldB<AT_P>(bv[0], ks_u, wn * 104, 0, b_row, b_kh, b_row2);
        #pragma unroll
        for (int st = 0; st < 5; ++st) {
            const int cur = st & 1, nxt = cur ^ 1;
            if (st + 1 < 5) {
                ldA(av[nxt],
                    qs_u + (uint32_t)(((wm * 16 + a_row) * AT_P + (st + 1) * 16 + a_kh) * 2));
                ldB<AT_P>(bv[nxt], ks_u, wn * 104, (st + 1) * 16, b_row, b_kh, b_row2);
            }
            applyAB(acc, av[cur], bv[cur]);
        }
    }

    const int g = lane >> 2, tg = lane & 3;
    #pragma unroll
    for (int nt = 0; nt < 13; ++nt) {
        int t2l = wn * 104 + nt * 8 + tg * 2;
        if (t2l < T2D) {
            float c0 = -0.0005f * k2s[t2l];
            float c1 = -0.0005f * k2s[t2l + 1];
            acc[nt][0] = fmaf(0.001f, acc[nt][0], c0);
            acc[nt][1] = fmaf(0.001f, acc[nt][1], c1);
            acc[nt][2] = fmaf(0.001f, acc[nt][2], c0);
            acc[nt][3] = fmaf(0.001f, acc[nt][3], c1);
        } else {
            acc[nt][0] = -1e30f; acc[nt][1] = -1e30f;
            acc[nt][2] = -1e30f; acc[nt][3] = -1e30f;
        }
    }

    float m0 = -1e30f, m1 = -1e30f;
    #pragma unroll
    for (int nt = 0; nt < 13; ++nt) {
        m0 = fmaxf(m0, fmaxf(acc[nt][0], acc[nt][1]));
        m1 = fmaxf(m1, fmaxf(acc[nt][2], acc[nt][3]));
    }
    #pragma unroll
    for (int off = 1; off < 4; off <<= 1) {
        m0 = fmaxf(m0, __shfl_xor_sync(0xffffffff, m0, off));
        m1 = fmaxf(m1, __shfl_xor_sync(0xffffffff, m1, off));
    }
    if (tg == 0) {
        redm[wn][wm * 16 + g] = m0;
        redm[wn][wm * 16 + g + 8] = m1;
    }
    __syncthreads();
    const float M0 = fmaxf(redm[0][wm * 16 + g], redm[1][wm * 16 + g]);
    const float M1 = fmaxf(redm[0][wm * 16 + g + 8], redm[1][wm * 16 + g + 8]);

    float s0 = 0.f, s1 = 0.f;
    #pragma unroll
    for (int nt = 0; nt < 13; ++nt) {
        s0 += __expf(acc[nt][0] - M0) + __expf(acc[nt][1] - M0);
        s1 += __expf(acc[nt][2] - M1) + __expf(acc[nt][3] - M1);
    }
    #pragma unroll
    for (int off = 1; off < 4; off <<= 1) {
        s0 += __shfl_xor_sync(0xffffffff, s0, off);
        s1 += __shfl_xor_sync(0xffffffff, s1, off);
    }
    if (tg == 0) {
        reds[wn][wm * 16 + g] = s0;
        reds[wn][wm * 16 + g + 8] = s1;
    }
    __syncthreads();
    const float L0 = M0 + __logf(reds[0][wm * 16 + g] + reds[1][wm * 16 + g]);
    const float L1 = M1 + __logf(reds[0][wm * 16 + g + 8] + reds[1][wm * 16 + g + 8]);

    const int row0 = t1base + wm * 16 + g;
    const int row1 = row0 + 8;
    #pragma unroll
    for (int nt = 0; nt < 13; ++nt) {
        int t2l = wn * 104 + nt * 8 + tg * 2;
        if (t2l < T2D) {
            size_t o0 = ((size_t)b * T1D + row0) * T2D + t2l;
            size_t o1 = ((size_t)b * T1D + row1) * T2D + t2l;
            float2 pr0 = *(const float2*)(prior + o0);
            float2 pr1 = *(const float2*)(prior + o1);
            float2 r0, r1;
            r0.x = acc[nt][0] - L0 + __logf(pr0.x + 1e-8f);
            r0.y = acc[nt][1] - L0 + __logf(pr0.y + 1e-8f);
            r1.x = acc[nt][2] - L1 + __logf(pr1.x + 1e-8f);
            r1.y = acc[nt][3] - L1 + __logf(pr1.y + 1e-8f);
            *(float2*)(out + o0) = r0;
            *(float2*)(out + o1) = r1;
        }
    }
}

// ---------------- launch ----------------
extern "C" void kernel_launch(void* const* d_in, const int* in_sizes, int n_in,
                              void* d_out, int out_size)
{
    const float* queries = (const float*)d_in[0];   // (16,80,800)
    const float* keys    = (const float*)d_in[1];   // (16,256,200)
    const float* prior   = (const float*)d_in[2];   // (16,800,200)
    const float* kw1     = (const float*)d_in[3];   // (512,256,3)
    const float* kb1     = (const float*)d_in[4];
    const float* kw2     = (const float*)d_in[5];   // (80,512,1)
    const float* kb2     = (const float*)d_in[6];
    const float* qw1     = (const float*)d_in[7];   // (160,80,3)
    const float* qb1     = (const float*)d_in[8];
    const float* qw2     = (const float*)d_in[9];   // (80,160,1)
    const float* qb2     = (const float*)d_in[10];
    const float* qw3     = (const float*)d_in[11];  // (80,80,1)
    const float* qb3     = (const float*)d_in[12];
    float* out = (float*)d_out;

    __nv_bfloat16 *xkp, *xqp, *k1ip, *q1ip, *kkip, *qqip;
    float* k2p;
    cudaGetSymbolAddress((void**)&xkp, g_xk);
    cudaGetSymbolAddress((void**)&xqp, g_xq);
    cudaGetSymbolAddress((void**)&k1ip, g_k1i);
    cudaGetSymbolAddress((void**)&q1ip, g_q1i);
    cudaGetSymbolAddress((void**)&kkip, g_kki);
    cudaGetSymbolAddress((void**)&qqip, g_qqi);
    cudaGetSymbolAddress((void**)&k2p, g_k2);

    constexpr int SM_KC1 = (106 * XK_P + 3 * 128 * 136) * 2;                  // 160,416
    constexpr int SM_QC3 = (106 * XQ_P + 3 * 80 * 88) * 2;                    //  60,896
    constexpr int SM_K11 = (104 * K1_P + 80 * 264) * 2 + 104 * 4;             // 154,144
    constexpr int SM_QF  = (104 * Q1_P + 80 * 168 + 104 * 88 + 80 * 88) * 2;  //  94,208

    cudaFuncSetAttribute((const void*)conv3_img_kernel<256, XK_P, 128, 8, K1_P>,
                         cudaFuncAttributeMaxDynamicSharedMemorySize, SM_KC1);
    cudaFuncSetAttribute((const void*)conv3_img_kernel<80, XQ_P, 80, 5, Q1_P>,
                         cudaFuncAttributeMaxDynamicSharedMemorySize, SM_QC3);
    cudaFuncSetAttribute((const void*)k11_kernel,
                         cudaFuncAttributeMaxDynamicSharedMemorySize, SM_K11);
    cudaFuncSetAttribute((const void*)qfused_kernel,
                         cudaFuncAttributeMaxDynamicSharedMemorySize, SM_QF);

    // prep: weight repack + input transposes
    prep_w_kernel<<<(W_TOTAL + 255) / 256, 256>>>(kw1, kw2, qw1, qw2, qw3);
    transpose_bf_kernel<<<dim3(7, 8, NB), dim3(32, 8)>>>(keys, xkp, 256, T2D, XK_P);
    transpose_bf_kernel<<<dim3(25, 3, NB), dim3(32, 8)>>>(queries, xqp, 80, T1D, XQ_P);

    // encoders
    conv3_img_kernel<256, XK_P, 128, 8, K1_P>
        <<<dim3(2, 4, NB), 256, SM_KC1>>>(xkp, OFF_KC1, kb1, k1ip, T2D);
    conv3_img_kernel<80, XQ_P, 80, 5, Q1_P>
        <<<dim3(8, 2, NB), 160, SM_QC3>>>(xqp, OFF_QC3, qb1, q1ip, T1D);
    k11_kernel<<<dim3(2, 1, NB), 160, SM_K11>>>(k1ip, kb2, kkip, k2p, T2D);
    qfused_kernel<<<dim3(8, 1, NB), 160, SM_QF>>>(q1ip, qb2, qb3, qqip, T1D);

    // attention (fully fused)
    attn_mma_kernel<<<dim3(25, NB), 128>>>(qqip, kkip, k2p, prior, out);
}

// round 15
// speedup vs baseline: 1.0813x; 1.0813x over previous
#include <cuda_runtime.h>
#include <cuda_bf16.h>
#include <math.h>
#include <stdint.h>

// ---------------- problem constants ----------------
// B=16, Cmel=80, Ctxt=256, Catt=80, T1=800, T2=200
#define NB   16
#define T1D  800
#define T2D  200

// t-major image strides (bf16 elems). Rule: (stride*2 bytes /4) mod 32 in {4,12,20,28}
#define XK_P 264   // keys    256+8
#define XQ_P 88    // queries  80+8
#define K1_P 536   // k1      512+24
#define Q1_P 168   // q1      160+8
#define AT_P 88    // q/k attention images 80+8

// ---------------- scratch (no allocation allowed) ----------------
__device__ __nv_bfloat16 g_wimg[522752];           // repacked weights
__device__ __nv_bfloat16 g_xk [NB * T2D * XK_P];   // keys bf16 t-major
__device__ __nv_bfloat16 g_xq [NB * T1D * XQ_P];   // queries bf16 t-major
__device__ __nv_bfloat16 g_k1i[NB * T2D * K1_P];   // key conv1 out, t-major
__device__ __nv_bfloat16 g_q1i[NB * T1D * Q1_P];   // query conv1 out, t-major
__device__ __nv_bfloat16 g_kki[NB * T2D * AT_P];   // k, t-major
__device__ __nv_bfloat16 g_qqi[NB * T1D * AT_P];   // q, t-major
__device__ float         g_k2 [NB * T2D];          // ||k||^2

// weight image section offsets (elems)
#define OFF_KC1 0
#define OFF_K11 417792
#define OFF_QC3 460032
#define OFF_Q12 502272
#define OFF_Q13 515712
#define W_TOTAL 522752

// ---------------- helpers ----------------
__device__ __forceinline__ uint32_t smem_u32(const void* p) {
    uint32_t a;
    asm("{ .reg .u64 t; cvta.to.shared.u64 t, %1; cvt.u32.u64 %0, t; }" : "=r"(a) : "l"(p));
    return a;
}
__device__ __forceinline__ void ldsm_x4(uint32_t& r0, uint32_t& r1, uint32_t& r2, uint32_t& r3,
                                        uint32_t addr) {
    asm volatile("ldmatrix.sync.aligned.m8n8.x4.shared.b16 {%0,%1,%2,%3}, [%4];"
                 : "=r"(r0), "=r"(r1), "=r"(r2), "=r"(r3) : "r"(addr));
}
__device__ __forceinline__ void ldsm_x2(uint32_t& r0, uint32_t& r1, uint32_t addr) {
    asm volatile("ldmatrix.sync.aligned.m8n8.x2.shared.b16 {%0,%1}, [%2];"
                 : "=r"(r0), "=r"(r1) : "r"(addr));
}
__device__ __forceinline__ void mma16816(float* c, uint32_t a0, uint32_t a1, uint32_t a2,
                                         uint32_t a3, uint32_t b0, uint32_t b1) {
    asm volatile("mma.sync.aligned.m16n8k16.row.col.f32.bf16.bf16.f32 "
                 "{%0,%1,%2,%3}, {%4,%5,%6,%7}, {%8,%9}, {%0,%1,%2,%3};"
                 : "+f"(c[0]), "+f"(c[1]), "+f"(c[2]), "+f"(c[3])
                 : "r"(a0), "r"(a1), "r"(a2), "r"(a3), "r"(b0), "r"(b1));
}

__device__ __forceinline__ void ldA(uint32_t (&av)[4], uint32_t addr) {
    ldsm_x4(av[0], av[1], av[2], av[3], addr);
}

// ---- 13-tile batch (104 n-cols per warp) : validated R12 path ----
template<int STR>
__device__ __forceinline__ void ldB13(uint32_t (&bv)[26], uint32_t xs_u, int row0, int colbase,
                                      int b_row, int b_kh, int b_row2) {
    #pragma unroll
    for (int p = 0; p < 6; ++p)
        ldsm_x4(bv[4 * p], bv[4 * p + 1], bv[4 * p + 2], bv[4 * p + 3],
                xs_u + (uint32_t)(((row0 + p * 16 + b_row) * STR + colbase + b_kh) * 2));
    ldsm_x2(bv[24], bv[25],
            xs_u + (uint32_t)(((row0 + 96 + b_row2) * STR + colbase + b_kh) * 2));
}
__device__ __forceinline__ void apply13(float (&acc)[13][4], const uint32_t (&av)[4],
                                        const uint32_t (&bv)[26]) {
    #pragma unroll
    for (int p = 0; p < 6; ++p) {
        mma16816(acc[2 * p],     av[0], av[1], av[2], av[3], bv[4 * p],     bv[4 * p + 1]);
        mma16816(acc[2 * p + 1], av[0], av[1], av[2], av[3], bv[4 * p + 2], bv[4 * p + 3]);
    }
    mma16816(acc[12], av[0], av[1], av[2], av[3], bv[24], bv[25]);
}

// ---- 7-tile batch (56 n-cols per warp) : for WN=2 conv3 ----
template<int STR>
__device__ __forceinline__ void ldB7(uint32_t (&bv)[14], uint32_t xs_u, int row0, int colbase,
                                     int b_row, int b_kh, int b_row2) {
    #pragma unroll
    for (int p = 0; p < 3; ++p)
        ldsm_x4(bv[4 * p], bv[4 * p + 1], bv[4 * p + 2], bv[4 * p + 3],
                xs_u + (uint32_t)(((row0 + p * 16 + b_row) * STR + colbase + b_kh) * 2));
    ldsm_x2(bv[12], bv[13],
            xs_u + (uint32_t)(((row0 + 48 + b_row2) * STR + colbase + b_kh) * 2));
}
__device__ __forceinline__ void apply7(float (&acc)[7][4], const uint32_t (&av)[4],
                                       const uint32_t (&bv)[14]) {
    #pragma unroll
    for (int p = 0; p < 3; ++p) {
        mma16816(acc[2 * p],     av[0], av[1], av[2], av[3], bv[4 * p],     bv[4 * p + 1]);
        mma16816(acc[2 * p + 1], av[0], av[1], av[2], av[3], bv[4 * p + 2], bv[4 * p + 3]);
    }
    mma16816(acc[6], av[0], av[1], av[2], av[3], bv[12], bv[13]);
}

// ---------------- weight repack: fp32 -> bf16 smem-image layout ----------------
__global__ void prep_w_kernel(const float* __restrict__ kw1, const float* __restrict__ kw2,
                              const float* __restrict__ qw1, const float* __restrict__ qw2,
                              const float* __restrict__ qw3)
{
    int idx = blockIdx.x * blockDim.x + threadIdx.x;
    if (idx >= W_TOTAL) return;
    float v = 0.f;
    if (idx < OFF_K11) {                       // key conv1: [y8][cc2][s3][co64][k136]
        int l = idx;
        int k = l % 136; l /= 136;
        int co = l % 64; l /= 64;
        int s = l % 3; l /= 3;
        int cc = l % 2; int y = l / 2;
        if (k < 128) v = kw1[(size_t)(y * 64 + co) * 768 + (cc * 128 + k) * 3 + s];
    } else if (idx < OFF_QC3) {                // key 1x1: [cc2][co80][k264]
        int l = idx - OFF_K11;
        int k = l % 264; l /= 264;
        int co = l % 80; int cc = l / 80;
        if (k < 256) v = kw2[(size_t)co * 512 + cc * 256 + k];
    } else if (idx < OFF_Q12) {                // q conv3: [y2][s3][co80][k88]
        int l = idx - OFF_QC3;
        int k = l % 88; l /= 88;
        int co = l % 80; l /= 80;
        int s = l % 3; int y = l / 3;
        if (k < 80) v = qw1[(size_t)(y * 80 + co) * 240 + k * 3 + s];
    } else if (idx < OFF_Q13) {                // q 1x1 a: [co80][k168]
        int l = idx - OFF_Q12;
        int k = l % 168; int co = l / 168;
        if (k < 160) v = qw2[(size_t)co * 160 + k];
    } else {                                   // q 1x1 b: [co80][k88]
        int l = idx - OFF_Q13;
        int k = l % 88; int co = l / 88;
        if (k < 80) v = qw3[(size_t)co * 80 + k];
    }
    g_wimg[idx] = __float2bfloat16(v);
}

// ---------------- input transpose: fp32 [C][T] -> bf16 [T][CP] ----------------
__global__ void transpose_bf_kernel(const float* __restrict__ x, __nv_bfloat16* __restrict__ out,
                                    int C, int T, int CP)
{
    __shared__ float tile[32][33];
    int b = blockIdx.z;
    int t0 = blockIdx.x * 32, c0 = blockIdx.y * 32;
    int tx = threadIdx.x, ty = threadIdx.y;
    #pragma unroll
    for (int j = 0; j < 4; ++j) {
        int c = c0 + ty + j * 8, t = t0 + tx;
        tile[ty + j * 8][tx] = (c < C && t < T) ? x[((size_t)b * C + c) * T + t] : 0.f;
    }
    __syncthreads();
    #pragma unroll
    for (int j = 0; j < 4; ++j) {
        int t = t0 + ty + j * 8, c = c0 + tx;
        if (t < T && c < C)
            out[((size_t)b * T + t) * CP + c] = __float2bfloat16(tile[tx][ty + j * 8]);
    }
}

// ---------------- k=3 conv + ReLU (v3): warps split co AND t ----------------
// WM x WN warps; warp (wm,wn): co rows wm*16..+15, 7 n-tiles at wn*56. BN=112.
template<int CIN, int CINP, int KC, int WM, int WN, int OUTP>
__global__ __launch_bounds__(32 * WM * WN)
void conv3_v3_kernel(const __nv_bfloat16* __restrict__ xin, int wimg_off,
                     const float* __restrict__ bias, __nv_bfloat16* __restrict__ yimg, int T)
{
    constexpr int THREADS = 32 * WM * WN;
    constexpr int BM = 16 * WM, BN = 56 * WN, ROWS = BN + 2;
    constexpr int KCP = KC + 8, NCH = CIN / KC;
    constexpr int XV = CINP / 8;
    constexpr int WCH = 3 * BM * KCP;
    constexpr int BMP = BM + 8;
    constexpr int KC16 = KC / 16;

    extern __shared__ __align__(16) char sm[];
    __nv_bfloat16* xs = (__nv_bfloat16*)sm;
    __nv_bfloat16* ws = xs + ROWS * CINP;
    __nv_bfloat16* os = xs;

    const int b = blockIdx.z, yb = blockIdx.y, t0 = blockIdx.x * BN;
    const int co0 = yb * BM;
    const int tid = threadIdx.x, lane = tid & 31, warp = tid >> 5;
    const int wm = warp % WM, wn = warp / WM;

    float acc[7][4];
    #pragma unroll
    for (int nt = 0; nt < 7; ++nt)
        #pragma unroll
        for (int i = 0; i < 4; ++i) acc[nt][i] = 0.f;

    const uint4 z4 = make_uint4(0, 0, 0, 0);
    for (int idx = tid; idx < ROWS * XV; idx += THREADS) {
        int r = idx / XV, c = idx - r * XV;
        int t = t0 + r - 1;
        uint4 v = z4;
        if (t >= 0 && t < T) v = ((const uint4*)(xin + ((size_t)b * T + t) * CINP))[c];
        ((uint4*)xs)[idx] = v;
    }

    const uint32_t xs_u = smem_u32(xs), ws_u = smem_u32(ws);
    const int a_row = lane & 15, a_kh = (lane >> 4) * 8;
    const int b_row = (lane & 7) + ((lane >> 4) & 1) * 8;
    const int b_kh = ((lane >> 3) & 1) * 8;
    const int b_row2 = lane & 7;
    const int nbase = wn * 56;

    for (int cc = 0; cc < NCH; ++cc) {
        if (cc) __syncthreads();
        const uint4* wsrc = (const uint4*)(g_wimg + wimg_off + (size_t)(yb * NCH + cc) * WCH);
        for (int i = tid; i < WCH / 8; i += THREADS) ((uint4*)ws)[i] = wsrc[i];
        __syncthreads();

        #pragma unroll
        for (int s = 0; s < 3; ++s) {
            #pragma unroll
            for (int kk = 0; kk < KC16; ++kk) {
                uint32_t av[4], bv[14];
                ldA(av, ws_u + (uint32_t)(((s * BM + wm * 16 + a_row) * KCP
                                           + kk * 16 + a_kh) * 2));
                ldB7<CINP>(bv, xs_u, nbase + s, cc * KC + kk * 16, b_row, b_kh, b_row2);
                apply7(acc, av, bv);
            }
        }
    }

    __syncthreads();
    const int g = lane >> 2, tg = lane & 3;
    const int coA = wm * 16 + g, coB = coA + 8;
    const float bA = bias[co0 + coA], bB = bias[co0 + coB];
    #pragma unroll
    for (int nt = 0; nt < 7; ++nt) {
        int tl = nbase + nt * 8 + tg * 2;
        os[tl * BMP + coA]       = __float2bfloat16(fmaxf(acc[nt][0] + bA, 0.f));
        os[(tl + 1) * BMP + coA] = __float2bfloat16(fmaxf(acc[nt][1] + bA, 0.f));
        os[tl * BMP + coB]       = __float2bfloat16(fmaxf(acc[nt][2] + bB, 0.f));
        os[(tl + 1) * BMP + coB] = __float2bfloat16(fmaxf(acc[nt][3] + bB, 0.f));
    }
    __syncthreads();
    constexpr int OV = BM / 8;
    for (int idx = tid; idx < BN * OV; idx += THREADS) {
        int r = idx / OV, c = idx - r * OV;
        int t = t0 + r;
        if (t < T)
            ((uint4*)(yimg + ((size_t)b * T + t) * OUTP + co0))[c] =
                ((const uint4*)(os + r * BMP))[c];
    }
}

// ---------------- key 1x1 (512->80) + fused ||k||^2, t-major image out ----------------
__global__ __launch_bounds__(160)
void k11_kernel(const __nv_bfloat16* __restrict__ xin,
                const float* __restrict__ bias, __nv_bfloat16* __restrict__ yimg,
                float* __restrict__ k2, int T)
{
    constexpr int THREADS = 160, BN = 104;
    constexpr int CINP = K1_P, KC = 256, KCP = KC + 8, NCH = 2;
    constexpr int XV = CINP / 8;
    constexpr int WCH = 80 * KCP;

    extern __shared__ __align__(16) char sm[];
    __nv_bfloat16* xs = (__nv_bfloat16*)sm;
    __nv_bfloat16* ws = xs + BN * CINP;
    float* ss = (float*)(ws + WCH);
    __nv_bfloat16* os = xs;

    const int b = blockIdx.z, t0 = blockIdx.x * BN;
    const int tid = threadIdx.x, lane = tid & 31, wm = tid >> 5;

    float acc[13][4];
    #pragma unroll
    for (int nt = 0; nt < 13; ++nt)
        #pragma unroll
        for (int i = 0; i < 4; ++i) acc[nt][i] = 0.f;

    for (int i = tid; i < BN; i += THREADS) ss[i] = 0.f;

    const uint4 z4 = make_uint4(0, 0, 0, 0);
    for (int idx = tid; idx < BN * XV; idx += THREADS) {
        int r = idx / XV, c = idx - r * XV;
        int t = t0 + r;
        uint4 v = z4;
        if (t < T) v = ((const uint4*)(xin + ((size_t)b * T + t) * CINP))[c];
        ((uint4*)xs)[idx] = v;
    }

    const uint32_t xs_u = smem_u32(xs), ws_u = smem_u32(ws);
    const int a_row = lane & 15, a_kh = (lane >> 4) * 8;
    const int b_row = (lane & 7) + ((lane >> 4) & 1) * 8;
    const int b_kh = ((lane >> 3) & 1) * 8;
    const int b_row2 = lane & 7;

    for (int cc = 0; cc < NCH; ++cc) {
        if (cc) __syncthreads();
        const uint4* wsrc = (const uint4*)(g_wimg + OFF_K11 + (size_t)cc * WCH);
        for (int i = tid; i < WCH / 8; i += THREADS) ((uint4*)ws)[i] = wsrc[i];
        __syncthreads();

        #pragma unroll
        for (int kk = 0; kk < KC / 16; ++kk) {
            uint32_t av[4], bv[26];
            ldA(av, ws_u + (uint32_t)(((wm * 16 + a_row) * KCP + kk * 16 + a_kh) * 2));
            ldB13<CINP>(bv, xs_u, 0, cc * KC + kk * 16, b_row, b_kh, b_row2);
            apply13(acc, av, bv);
        }
    }

    __syncthreads();
    const int g = lane >> 2, tg = lane & 3;
    const int coA = wm * 16 + g, coB = coA + 8;
    const float bA = bias[coA], bB = bias[coB];
    #pragma unroll
    for (int nt = 0; nt < 13; ++nt) {
        int tl = nt * 8 + tg * 2;
        float v0 = acc[nt][0] + bA, v1 = acc[nt][1] + bA;
        float v2 = acc[nt][2] + bB, v3 = acc[nt][3] + bB;
        os[tl * AT_P + coA]       = __float2bfloat16(v0);
        os[(tl + 1) * AT_P + coA] = __float2bfloat16(v1);
        os[tl * AT_P + coB]       = __float2bfloat16(v2);
        os[(tl + 1) * AT_P + coB] = __float2bfloat16(v3);
        float s0 = v0 * v0 + v2 * v2;
        float s1 = v1 * v1 + v3 * v3;
        #pragma unroll
        for (int off = 4; off < 32; off <<= 1) {
            s0 += __shfl_xor_sync(0xffffffff, s0, off);
            s1 += __shfl_xor_sync(0xffffffff, s1, off);
        }
        if (g == 0) {
            atomicAdd(&ss[tl], s0);
            atomicAdd(&ss[tl + 1], s1);
        }
    }
    __syncthreads();
    constexpr int OV = AT_P / 8;
    for (int idx = tid; idx < BN * OV; idx += THREADS) {
        int r = idx / OV, c = idx - r * OV;
        int t = t0 + r;
        if (t < T)
            ((uint4*)(yimg + ((size_t)b * T + t) * AT_P))[c] =
                ((const uint4*)(os + r * AT_P))[c];
    }
    for (int i = tid; i < BN; i += THREADS) {
        int t = t0 + i;
        if (t < T) k2[b * T2D + t] = ss[i];
    }
}

// ---------------- fused query 1x1 (160->80 relu) -> 1x1 (80->80), t-major out ----------------
__global__ __launch_bounds__(160)
void qfused_kernel(const __nv_bfloat16* __restrict__ xin, const float* __restrict__ b2,
                   const float* __restrict__ b3, __nv_bfloat16* __restrict__ yimg, int T)
{
    constexpr int THREADS = 160, BN = 104;
    constexpr int CINP1 = Q1_P;   // 168
    constexpr int KCP2 = 168, KCP3 = 88, QMP = 88;

    extern __shared__ __align__(16) char sm[];
    __nv_bfloat16* xs  = (__nv_bfloat16*)sm;          // [104][168]
    __nv_bfloat16* w2s = xs + BN * CINP1;             // [80][168]
    __nv_bfloat16* qms = w2s + 80 * KCP2;             // [104][88]
    __nv_bfloat16* w3s = qms + BN * QMP;              // [80][88]
    __nv_bfloat16* os  = xs;

    const int b = blockIdx.z, t0 = blockIdx.x * BN;
    const int tid = threadIdx.x, lane = tid & 31, wm = tid >> 5;

    float acc[13][4];
    #pragma unroll
    for (int nt = 0; nt < 13; ++nt)
        #pragma unroll
        for (int i = 0; i < 4; ++i) acc[nt][i] = 0.f;

    const uint4 z4 = make_uint4(0, 0, 0, 0);
    constexpr int XV = CINP1 / 8;
    for (int idx = tid; idx < BN * XV; idx += THREADS) {
        int r = idx / XV, c = idx - r * XV;
        int t = t0 + r;
        uint4 v = z4;
        if (t < T) v = ((const uint4*)(xin + ((size_t)b * T + t) * CINP1))[c];
        ((uint4*)xs)[idx] = v;
    }
    {
        const uint4* s2 = (const uint4*)(g_wimg + OFF_Q12);
        for (int i = tid; i < 80 * KCP2 / 8; i += THREADS) ((uint4*)w2s)[i] = s2[i];
        const uint4* s3 = (const uint4*)(g_wimg + OFF_Q13);
        for (int i = tid; i < 80 * KCP3 / 8; i += THREADS) ((uint4*)w3s)[i] = s3[i];
    }
    __syncthreads();

    const uint32_t xs_u = smem_u32(xs), w2_u = smem_u32(w2s);
    const uint32_t qm_u = smem_u32(qms), w3_u = smem_u32(w3s);
    const int a_row = lane & 15, a_kh = (lane >> 4) * 8;
    const int b_row = (lane & 7) + ((lane >> 4) & 1) * 8;
    const int b_kh = ((lane >> 3) & 1) * 8;
    const int b_row2 = lane & 7;
    const int g = lane >> 2, tg = lane & 3;
    const int coA = wm * 16 + g, coB = coA + 8;

    // stage 1: q1 (160) -> qm (80), relu
    #pragma unroll
    for (int kk = 0; kk < 10; ++kk) {
        uint32_t av[4], bv[26];
        ldA(av, w2_u + (uint32_t)(((wm * 16 + a_row) * KCP2 + kk * 16 + a_kh) * 2));
        ldB13<CINP1>(bv, xs_u, 0, kk * 16, b_row, b_kh, b_row2);
        apply13(acc, av, bv);
    }
    {
        const float bA = b2[coA], bB = b2[coB];
        #pragma unroll
        for (int nt = 0; nt < 13; ++nt) {
            int tl = nt * 8 + tg * 2;
            qms[tl * QMP + coA]       = __float2bfloat16(fmaxf(acc[nt][0] + bA, 0.f));
            qms[(tl + 1) * QMP + coA] = __float2bfloat16(fmaxf(acc[nt][1] + bA, 0.f));
            qms[tl * QMP + coB]       = __float2bfloat16(fmaxf(acc[nt][2] + bB, 0.f));
            qms[(tl + 1) * QMP + coB] = __float2bfloat16(fmaxf(acc[nt][3] + bB, 0.f));
            #pragma unroll
            for (int i = 0; i < 4; ++i) acc[nt][i] = 0.f;
        }
    }
    __syncthreads();

    // stage 2: qm (80) -> q (80)
    #pragma unroll
    for (int kk = 0; kk < 5; ++kk) {
        uint32_t av[4], bv[26];
        ldA(av, w3_u + (uint32_t)(((wm * 16 + a_row) * KCP3 + kk * 16 + a_kh) * 2));
        ldB13<QMP>(bv, qm_u, 0, kk * 16, b_row, b_kh, b_row2);
        apply13(acc, av, bv);
    }
    {
        const float bA = b3[coA], bB = b3[coB];
        #pragma unroll
        for (int nt = 0; nt < 13; ++nt) {
            int tl = nt * 8 + tg * 2;
            os[tl * AT_P + coA]       = __float2bfloat16(acc[nt][0] + bA);
            os[(tl + 1) * AT_P + coA] = __float2bfloat16(acc[nt][1] + bA);
            os[tl * AT_P + coB]       = __float2bfloat16(acc[nt][2] + bB);
            os[(tl + 1) * AT_P + coB] = __float2bfloat16(acc[nt][3] + bB);
        }
    }
    __syncthreads();
    constexpr int OV = AT_P / 8;
    for (int idx = tid; idx < BN * OV; idx += THREADS) {
        int r = idx / OV, c = idx - r * OV;
        int t = t0 + r;
        if (t < T)
            ((uint4*)(yimg + ((size_t)b * T + t) * AT_P))[c] =
                ((const uint4*)(os + r * AT_P))[c];
    }
}

// ---------------- attention: mma logits + fused log_softmax + log(prior) ----------------
__global__ __launch_bounds__(128)
void attn_mma_kernel(const __nv_bfloat16* __restrict__ qimg,
                     const __nv_bfloat16* __restrict__ kimg,
                     const float* __restrict__ k2, const float* __restrict__ prior,
                     float* __restrict__ out)
{
    constexpr int KROWS = 208;
    __shared__ __nv_bfloat16 ks[KROWS * AT_P];
    __shared__ __nv_bfloat16 qs[32 * AT_P];
    __shared__ float k2s[T2D];
    __shared__ float redm[2][32], reds[2][32];

    const int b = blockIdx.y, t1base = blockIdx.x * 32;
    const int tid = threadIdx.x, lane = tid & 31, warp = tid >> 5;
    const int wm = warp & 1, wn = warp >> 1;

    constexpr int KV = AT_P / 8;
    const uint4 z4 = make_uint4(0, 0, 0, 0);
    for (int idx = tid; idx < KROWS * KV; idx += 128) {
        int r = idx / KV, c = idx - r * KV;
        uint4 v = z4;
        if (r < T2D) v = ((const uint4*)(kimg + ((size_t)b * T2D + r) * AT_P))[c];
        ((uint4*)ks)[idx] = v;
    }
    for (int idx = tid; idx < 32 * KV; idx += 128) {
        int r = idx / KV, c = idx - r * KV;
        ((uint4*)qs)[idx] = ((const uint4*)(qimg + ((size_t)b * T1D + t1base + r) * AT_P))[c];
    }
    for (int i = tid; i < T2D; i += 128) k2s[i] = k2[b * T2D + i];
    __syncthreads();

    float acc[13][4];
    #pragma unroll
    for (int nt = 0; nt < 13; ++nt)
        #pragma unroll
        for (int i = 0; i < 4; ++i) acc[nt][i] = 0.f;

    const uint32_t qs_u = smem_u32(qs), ks_u = smem_u32(ks);
    const int a_row = lane & 15, a_kh = (lane >> 4) * 8;
    const int b_row = (lane & 7) + ((lane >> 4) & 1) * 8;
    const int b_kh = ((lane >> 3) & 1) * 8;
    const int b_row2 = lane & 7;

    #pragma unroll
    for (int kk = 0; kk < 5; ++kk) {
        uint32_t av[4], bv[26];
        ldA(av, qs_u + (uint32_t)(((wm * 16 + a_row) * AT_P + kk * 16 + a_kh) * 2));
        ldB13<AT_P>(bv, ks_u, wn * 104, kk * 16, b_row, b_kh, b_row2);
        apply13(acc, av, bv);
    }

    const int g = lane >> 2, tg = lane & 3;
    #pragma unroll
    for (int nt = 0; nt < 13; ++nt) {
        int t2l = wn * 104 + nt * 8 + tg * 2;
        if (t2l < T2D) {
            float c0 = -0.0005f * k2s[t2l];
            float c1 = -0.0005f * k2s[t2l + 1];
            acc[nt][0] = fmaf(0.001f, acc[nt][0], c0);
            acc[nt][1] = fmaf(0.001f, acc[nt][1], c1);
            acc[nt][2] = fmaf(0.001f, acc[nt][2], c0);
            acc[nt][3] = fmaf(0.001f, acc[nt][3], c1);
        } else {
            acc[nt][0] = -1e30f; acc[nt][1] = -1e30f;
            acc[nt][2] = -1e30f; acc[nt][3] = -1e30f;
        }
    }

    float m0 = -1e30f, m1 = -1e30f;
    #pragma unroll
    for (int nt = 0; nt < 13; ++nt) {
        m0 = fmaxf(m0, fmaxf(acc[nt][0], acc[nt][1]));
        m1 = fmaxf(m1, fmaxf(acc[nt][2], acc[nt][3]));
    }
    #pragma unroll
    for (int off = 1; off < 4; off <<= 1) {
        m0 = fmaxf(m0, __shfl_xor_sync(0xffffffff, m0, off));
        m1 = fmaxf(m1, __shfl_xor_sync(0xffffffff, m1, off));
    }
    if (tg == 0) {
        redm[wn][wm * 16 + g] = m0;
        redm[wn][wm * 16 + g + 8] = m1;
    }
    __syncthreads();
    const float M0 = fmaxf(redm[0][wm * 16 + g], redm[1][wm * 16 + g]);
    const float M1 = fmaxf(redm[0][wm * 16 + g + 8], redm[1][wm * 16 + g + 8]);

    float s0 = 0.f, s1 = 0.f;
    #pragma unroll
    for (int nt = 0; nt < 13; ++nt) {
        s0 += __expf(acc[nt][0] - M0) + __expf(acc[nt][1] - M0);
        s1 += __expf(acc[nt][2] - M1) + __expf(acc[nt][3] - M1);
    }
    #pragma unroll
    for (int off = 1; off < 4; off <<= 1) {
        s0 += __shfl_xor_sync(0xffffffff, s0, off);
        s1 += __shfl_xor_sync(0xffffffff, s1, off);
    }
    if (tg == 0) {
        reds[wn][wm * 16 + g] = s0;
        reds[wn][wm * 16 + g + 8] = s1;
    }
    __syncthreads();
    const float L0 = M0 + __logf(reds[0][wm * 16 + g] + reds[1][wm * 16 + g]);
    const float L1 = M1 + __logf(reds[0][wm * 16 + g + 8] + reds[1][wm * 16 + g + 8]);

    const int row0 = t1base + wm * 16 + g;
    const int row1 = row0 + 8;
    #pragma unroll
    for (int nt = 0; nt < 13; ++nt) {
        int t2l = wn * 104 + nt * 8 + tg * 2;
        if (t2l < T2D) {
            size_t o0 = ((size_t)b * T1D + row0) * T2D + t2l;
            size_t o1 = ((size_t)b * T1D + row1) * T2D + t2l;
            float2 pr0 = *(const float2*)(prior + o0);
            float2 pr1 = *(const float2*)(prior + o1);
            float2 r0, r1;
            r0.x = acc[nt][0] - L0 + __logf(pr0.x + 1e-8f);
            r0.y = acc[nt][1] - L0 + __logf(pr0.y + 1e-8f);
            r1.x = acc[nt][2] - L1 + __logf(pr1.x + 1e-8f);
            r1.y = acc[nt][3] - L1 + __logf(pr1.y + 1e-8f);
            *(float2*)(out + o0) = r0;
            *(float2*)(out + o1) = r1;
        }
    }
}

// ---------------- launch ----------------
extern "C" void kernel_launch(void* const* d_in, const int* in_sizes, int n_in,
                              void* d_out, int out_size)
{
    const float* queries = (const float*)d_in[0];   // (16,80,800)
    const float* keys    = (const float*)d_in[1];   // (16,256,200)
    const float* prior   = (const float*)d_in[2];   // (16,800,200)
    const float* kw1     = (const float*)d_in[3];   // (512,256,3)
    const float* kb1     = (const float*)d_in[4];
    const float* kw2     = (const float*)d_in[5];   // (80,512,1)
    const float* kb2     = (const float*)d_in[6];
    const float* qw1     = (const float*)d_in[7];   // (160,80,3)
    const float* qb1     = (const float*)d_in[8];
    const float* qw2     = (const float*)d_in[9];   // (80,160,1)
    const float* qb2     = (const float*)d_in[10];
    const float* qw3     = (const float*)d_in[11];  // (80,80,1)
    const float* qb3     = (const float*)d_in[12];
    float* out = (float*)d_out;

    __nv_bfloat16 *xkp, *xqp, *k1ip, *q1ip, *kkip, *qqip;
    float* k2p;
    cudaGetSymbolAddress((void**)&xkp, g_xk);
    cudaGetSymbolAddress((void**)&xqp, g_xq);
    cudaGetSymbolAddress((void**)&k1ip, g_k1i);
    cudaGetSymbolAddress((void**)&q1ip, g_q1i);
    cudaGetSymbolAddress((void**)&kkip, g_kki);
    cudaGetSymbolAddress((void**)&qqip, g_qqi);
    cudaGetSymbolAddress((void**)&k2p, g_k2);

    // dynamic smem sizes
    constexpr int SM_KC1 = (114 * XK_P + 3 * 64 * 136) * 2;                   // 112,416 -> 2 blocks/SM
    constexpr int SM_QC3 = (114 * XQ_P + 3 * 80 * 88) * 2;                    //  62,304 -> 2-3 blocks/SM
    constexpr int SM_K11 = (104 * K1_P + 80 * 264) * 2 + 104 * 4;             // 154,144
    constexpr int SM_QF  = (104 * Q1_P + 80 * 168 + 104 * 88 + 80 * 88) * 2;  //  94,208

    cudaFuncSetAttribute((const void*)conv3_v3_kernel<256, XK_P, 128, 4, 2, K1_P>,
                         cudaFuncAttributeMaxDynamicSharedMemorySize, SM_KC1);
    cudaFuncSetAttribute((const void*)conv3_v3_kernel<80, XQ_P, 80, 5, 2, Q1_P>,
                         cudaFuncAttributeMaxDynamicSharedMemorySize, SM_QC3);
    cudaFuncSetAttribute((const void*)k11_kernel,
                         cudaFuncAttributeMaxDynamicSharedMemorySize, SM_K11);
    cudaFuncSetAttribute((const void*)qfused_kernel,
                         cudaFuncAttributeMaxDynamicSharedMemorySize, SM_QF);

    // prep: weight repack + input transposes
    prep_w_kernel<<<(W_TOTAL + 255) / 256, 256>>>(kw1, kw2, qw1, qw2, qw3);
    transpose_bf_kernel<<<dim3(7, 8, NB), dim3(32, 8)>>>(keys, xkp, 256, T2D, XK_P);
    transpose_bf_kernel<<<dim3(25, 3, NB), dim3(32, 8)>>>(queries, xqp, 80, T1D, XQ_P);

    // encoders
    // kc1: BM=64 (WM=4, WN=2, 256 thr), BN=112, grid 2x8x16 = 256 blocks
    conv3_v3_kernel<256, XK_P, 128, 4, 2, K1_P>
        <<<dim3(2, 8, NB), 256, SM_KC1>>>(xkp, OFF_KC1, kb1, k1ip, T2D);
    // qc3: BM=80 (WM=5, WN=2, 320 thr), BN=112, grid 8x2x16 = 256 blocks
    conv3_v3_kernel<80, XQ_P, 80, 5, 2, Q1_P>
        <<<dim3(8, 2, NB), 320, SM_QC3>>>(xqp, OFF_QC3, qb1, q1ip, T1D);
    k11_kernel<<<dim3(2, 1, NB), 160, SM_K11>>>(k1ip, kb2, kkip, k2p, T2D);
    qfused_kernel<<<dim3(8, 1, NB), 160, SM_QF>>>(q1ip, qb2, qb3, qqip, T1D);

    // attention (fully fused)
    attn_mma_kernel<<<dim3(25, NB), 128>>>(qqip, kkip, k2p, prior, out);
}